// round 2
// baseline (speedup 1.0000x reference)
#include <cuda_runtime.h>
#include <cstdint>

#define N_RES 8192
#define N_IN  256
#define BATCH 16
#define MAX_NNZ_RES 6720000   // actual: 6,710,886

// ---- device scratch (static; no runtime allocation allowed) ----
__device__ float              g_ZT[N_RES * BATCH];  // bias + input-matrix part, [row][b]
__device__ float              g_ST[N_RES * BATCH];  // state^T, [col][b]
__device__ float              g_XT[N_IN  * BATCH];  // x^T, [col][b]
__device__ int                g_base[N_RES + 1];    // CSR row offsets (immutable after scan)
__device__ int                g_cursor[N_RES];      // mutable write cursors
__device__ int                g_counts[N_RES];      // histogram
__device__ unsigned long long g_csr[MAX_NNZ_RES];   // packed (col<<32 | val_bits)

__device__ __forceinline__ void red_add_v4(float* addr, float a, float b, float c, float d) {
    asm volatile("red.global.add.v4.f32 [%0], {%1, %2, %3, %4};"
                 :: "l"(addr), "f"(a), "f"(b), "f"(c), "f"(d)
                 : "memory");
}

// 1) transposes + ZT=bias + zero histogram
__global__ void prep_kernel(const float* __restrict__ state,
                            const float* __restrict__ x,
                            const float* __restrict__ bias) {
    int t = blockIdx.x * blockDim.x + threadIdx.x;
    if (t < N_RES * BATCH) {
        int b = t >> 13;
        int r = t & (N_RES - 1);
        g_ST[r * BATCH + b] = state[t];
        g_ZT[r * BATCH + b] = bias[r];
    }
    if (t < N_IN * BATCH) {
        int b = t >> 8;
        int c = t & (N_IN - 1);
        g_XT[c * BATCH + b] = x[t];
    }
    if (t < N_RES) g_counts[t] = 0;
}

// 2) row histogram (RED.ADD, result unused)
__global__ void hist_kernel(const int* __restrict__ res_rows, int nnz) {
    int i = blockIdx.x * blockDim.x + threadIdx.x;
    if (i < nnz) atomicAdd(&g_counts[res_rows[i]], 1);
}

// 3) exclusive scan of 8192 counts -> g_base, g_cursor  (single block, 1024 threads)
__global__ void scan_kernel() {
    __shared__ int warpsum[32];
    int tid  = threadIdx.x;
    int lane = tid & 31;
    int w    = tid >> 5;
    int base = tid * 8;

    int v[8];
    int s = 0;
#pragma unroll
    for (int k = 0; k < 8; k++) { v[k] = g_counts[base + k]; s += v[k]; }

    // inclusive warp scan of per-thread sums
    int ss = s;
#pragma unroll
    for (int o = 1; o < 32; o <<= 1) {
        int n = __shfl_up_sync(0xffffffffu, ss, o);
        if (lane >= o) ss += n;
    }
    if (lane == 31) warpsum[w] = ss;
    __syncthreads();
    if (w == 0) {
        int t = warpsum[lane];
#pragma unroll
        for (int o = 1; o < 32; o <<= 1) {
            int n = __shfl_up_sync(0xffffffffu, t, o);
            if (lane >= o) t += n;
        }
        warpsum[lane] = t;
    }
    __syncthreads();

    int off = (w > 0 ? warpsum[w - 1] : 0) + ss - s;  // exclusive base for this thread
    int run = off;
#pragma unroll
    for (int k = 0; k < 8; k++) {
        g_base[base + k]   = run;
        g_cursor[base + k] = run;
        run += v[k];
    }
    if (tid == 1023) g_base[N_RES] = run;
}

// 4) scatter COO -> CSR order, (col,val) packed into one 8B store
__global__ void scatter_kernel(const float* __restrict__ res_vals,
                               const int*   __restrict__ res_rows,
                               const int*   __restrict__ res_cols, int nnz) {
    int i = blockIdx.x * blockDim.x + threadIdx.x;
    if (i >= nnz) return;
    int   row = res_rows[i];
    int   col = res_cols[i];
    float val = res_vals[i];
    int pos = atomicAdd(&g_cursor[row], 1);
    g_csr[pos] = ((unsigned long long)(unsigned)col << 32) | (unsigned)__float_as_uint(val);
}

// 5) small input-matrix contribution via vector global reductions into ZT
__global__ void in_spmm_kernel(const float* __restrict__ in_vals,
                               const int*   __restrict__ in_rows,
                               const int*   __restrict__ in_cols, int nnz) {
    int i = blockIdx.x * blockDim.x + threadIdx.x;
    if (i >= nnz) return;
    float val = in_vals[i];
    int   row = in_rows[i];
    int   col = in_cols[i];
    const float4* src = reinterpret_cast<const float4*>(g_XT) + col * 4;
    float4 s0 = src[0], s1 = src[1], s2 = src[2], s3 = src[3];
    float* dst = g_ZT + row * BATCH;
    red_add_v4(dst +  0, val * s0.x, val * s0.y, val * s0.z, val * s0.w);
    red_add_v4(dst +  4, val * s1.x, val * s1.y, val * s1.z, val * s1.w);
    red_add_v4(dst +  8, val * s2.x, val * s2.y, val * s2.z, val * s2.w);
    red_add_v4(dst + 12, val * s3.x, val * s3.y, val * s3.z, val * s3.w);
}

// 6) warp-per-row CSR SpMM, register accumulators, butterfly reduce, fused erf+transpose
__global__ void csr_spmm_kernel(float* __restrict__ out) {
    int warp_id = (blockIdx.x * blockDim.x + threadIdx.x) >> 5;
    int lane    = threadIdx.x & 31;
    if (warp_id >= N_RES) return;
    int row   = warp_id;
    int start = g_base[row];
    int end   = g_base[row + 1];

    float acc[16];
#pragma unroll
    for (int k = 0; k < 16; k++) acc[k] = 0.0f;

    for (int j = start + lane; j < end; j += 32) {
        unsigned long long e = g_csr[j];
        float val = __uint_as_float((unsigned)e);
        int   col = (int)(e >> 32);
        const float4* src = reinterpret_cast<const float4*>(g_ST) + col * 4;
        float4 s0 = src[0], s1 = src[1], s2 = src[2], s3 = src[3];
        acc[0]  += val * s0.x;  acc[1]  += val * s0.y;
        acc[2]  += val * s0.z;  acc[3]  += val * s0.w;
        acc[4]  += val * s1.x;  acc[5]  += val * s1.y;
        acc[6]  += val * s1.z;  acc[7]  += val * s1.w;
        acc[8]  += val * s2.x;  acc[9]  += val * s2.y;
        acc[10] += val * s2.z;  acc[11] += val * s2.w;
        acc[12] += val * s3.x;  acc[13] += val * s3.y;
        acc[14] += val * s3.z;  acc[15] += val * s3.w;
    }

    // butterfly reduce each accumulator across the warp (all lanes end with totals)
#pragma unroll
    for (int k = 0; k < 16; k++) {
#pragma unroll
        for (int o = 16; o > 0; o >>= 1)
            acc[k] += __shfl_xor_sync(0xffffffffu, acc[k], o);
    }

    if (lane < 16) {
        float z = acc[lane] + g_ZT[row * BATCH + lane];
        out[lane * N_RES + row] = erff(z);
    }
}

extern "C" void kernel_launch(void* const* d_in, const int* in_sizes, int n_in,
                              void* d_out, int out_size) {
    const float* state    = (const float*)d_in[0];
    const float* x        = (const float*)d_in[1];
    const float* res_vals = (const float*)d_in[2];
    const int*   res_rows = (const int*)  d_in[3];
    const int*   res_cols = (const int*)  d_in[4];
    const float* res_bias = (const float*)d_in[5];
    const float* in_vals  = (const float*)d_in[6];
    const int*   in_rows  = (const int*)  d_in[7];
    const int*   in_cols  = (const int*)  d_in[8];
    float* out = (float*)d_out;

    int nnz_res = in_sizes[2];
    int nnz_in  = in_sizes[6];

    const int TPB = 256;

    prep_kernel<<<(N_RES * BATCH + TPB - 1) / TPB, TPB>>>(state, x, res_bias);
    hist_kernel<<<(nnz_res + TPB - 1) / TPB, TPB>>>(res_rows, nnz_res);
    scan_kernel<<<1, 1024>>>();
    scatter_kernel<<<(nnz_res + TPB - 1) / TPB, TPB>>>(res_vals, res_rows, res_cols, nnz_res);
    in_spmm_kernel<<<(nnz_in + TPB - 1) / TPB, TPB>>>(in_vals, in_rows, in_cols, nnz_in);
    csr_spmm_kernel<<<(N_RES * 32 + TPB - 1) / TPB, TPB>>>(out);
}

// round 3
// speedup vs baseline: 1.9409x; 1.9409x over previous
#include <cuda_runtime.h>
#include <cstdint>

#define N_RES 8192
#define N_IN  256
#define BATCH 16

// Scratch (device globals — allocation at runtime is prohibited)
__device__ __align__(256) float g_ZT[N_RES * BATCH];   // accumulator, [row][b], 64B rows
__device__ __align__(256) float g_ST[N_RES * BATCH];   // state^T, [col][b]
__device__ __align__(256) float g_XT[N_IN * BATCH];    // x^T, [col][b]

// One nnz: gather 64B (16 f32) from sptr, multiply by val (packed f32x2),
// vector-reduce 64B into dst. All in one asm block so the b64<->f32 splits
// fold into register pairing.
__device__ __forceinline__ void nnz_update(const float* sptr, float* dst, float val) {
    asm volatile("{\n\t"
        ".reg .b64 g0,g1,g2,g3,g4,g5,g6,g7;\n\t"
        ".reg .b64 pv,q0,q1,q2,q3,q4,q5,q6,q7;\n\t"
        ".reg .f32 a0,a1,a2,a3,a4,a5,a6,a7,a8,a9,a10,a11,a12,a13,a14,a15;\n\t"
        "mov.b64 pv, {%2,%2};\n\t"
        "ld.global.nc.v2.b64 {g0,g1}, [%0];\n\t"
        "ld.global.nc.v2.b64 {g2,g3}, [%0+16];\n\t"
        "ld.global.nc.v2.b64 {g4,g5}, [%0+32];\n\t"
        "ld.global.nc.v2.b64 {g6,g7}, [%0+48];\n\t"
        "mul.rn.f32x2 q0, pv, g0;\n\t"
        "mul.rn.f32x2 q1, pv, g1;\n\t"
        "mul.rn.f32x2 q2, pv, g2;\n\t"
        "mul.rn.f32x2 q3, pv, g3;\n\t"
        "mul.rn.f32x2 q4, pv, g4;\n\t"
        "mul.rn.f32x2 q5, pv, g5;\n\t"
        "mul.rn.f32x2 q6, pv, g6;\n\t"
        "mul.rn.f32x2 q7, pv, g7;\n\t"
        "mov.b64 {a0,a1},   q0;\n\t"
        "mov.b64 {a2,a3},   q1;\n\t"
        "mov.b64 {a4,a5},   q2;\n\t"
        "mov.b64 {a6,a7},   q3;\n\t"
        "mov.b64 {a8,a9},   q4;\n\t"
        "mov.b64 {a10,a11}, q5;\n\t"
        "mov.b64 {a12,a13}, q6;\n\t"
        "mov.b64 {a14,a15}, q7;\n\t"
        "red.global.add.v4.f32 [%1],    {a0,a1,a2,a3};\n\t"
        "red.global.add.v4.f32 [%1+16], {a4,a5,a6,a7};\n\t"
        "red.global.add.v4.f32 [%1+32], {a8,a9,a10,a11};\n\t"
        "red.global.add.v4.f32 [%1+48], {a12,a13,a14,a15};\n\t"
        "}" :: "l"(sptr), "l"(dst), "f"(val) : "memory");
}

// prep: transpose state -> ST, x -> XT, init ZT[r][b] = bias[r]
__global__ void prep_kernel(const float* __restrict__ state,
                            const float* __restrict__ x,
                            const float* __restrict__ bias) {
    int t = blockIdx.x * blockDim.x + threadIdx.x;
    if (t < N_RES * BATCH) {
        int b = t >> 13;
        int r = t & (N_RES - 1);
        g_ST[r * BATCH + b] = state[t];
        g_ZT[r * BATCH + b] = bias[r];
    }
    if (t < N_IN * BATCH) {
        int b = t >> 8;
        int c = t & (N_IN - 1);
        g_XT[c * BATCH + b] = x[t];
    }
}

// reservoir SpMM: 4 nnz per thread, vectorized COO loads
__global__ void spmm_kernel(const float* __restrict__ vals,
                            const int*   __restrict__ rows,
                            const int*   __restrict__ cols, int nnz) {
    int g  = blockIdx.x * blockDim.x + threadIdx.x;
    int i0 = g * 4;
    if (i0 + 4 <= nnz) {
        float4 v = *reinterpret_cast<const float4*>(vals + i0);
        int4   r = *reinterpret_cast<const int4*>(rows + i0);
        int4   c = *reinterpret_cast<const int4*>(cols + i0);
        nnz_update(g_ST + c.x * BATCH, g_ZT + r.x * BATCH, v.x);
        nnz_update(g_ST + c.y * BATCH, g_ZT + r.y * BATCH, v.y);
        nnz_update(g_ST + c.z * BATCH, g_ZT + r.z * BATCH, v.z);
        nnz_update(g_ST + c.w * BATCH, g_ZT + r.w * BATCH, v.w);
    } else if (i0 < nnz) {
        for (int i = i0; i < nnz; i++)
            nnz_update(g_ST + cols[i] * BATCH, g_ZT + rows[i] * BATCH, vals[i]);
    }
}

// input-matrix SpMM (small): same update against XT
__global__ void in_spmm_kernel(const float* __restrict__ vals,
                               const int*   __restrict__ rows,
                               const int*   __restrict__ cols, int nnz) {
    int g  = blockIdx.x * blockDim.x + threadIdx.x;
    int i0 = g * 4;
    if (i0 + 4 <= nnz) {
        float4 v = *reinterpret_cast<const float4*>(vals + i0);
        int4   r = *reinterpret_cast<const int4*>(rows + i0);
        int4   c = *reinterpret_cast<const int4*>(cols + i0);
        nnz_update(g_XT + c.x * BATCH, g_ZT + r.x * BATCH, v.x);
        nnz_update(g_XT + c.y * BATCH, g_ZT + r.y * BATCH, v.y);
        nnz_update(g_XT + c.z * BATCH, g_ZT + r.z * BATCH, v.z);
        nnz_update(g_XT + c.w * BATCH, g_ZT + r.w * BATCH, v.w);
    } else if (i0 < nnz) {
        for (int i = i0; i < nnz; i++)
            nnz_update(g_XT + cols[i] * BATCH, g_ZT + rows[i] * BATCH, vals[i]);
    }
}

// finish: out[b][r] = erf(ZT[r][b])
__global__ void finish_kernel(float* __restrict__ out) {
    int t = blockIdx.x * blockDim.x + threadIdx.x;
    if (t >= N_RES * BATCH) return;
    int b = t >> 13;
    int r = t & (N_RES - 1);
    out[t] = erff(g_ZT[r * BATCH + b]);
}

extern "C" void kernel_launch(void* const* d_in, const int* in_sizes, int n_in,
                              void* d_out, int out_size) {
    const float* state    = (const float*)d_in[0];
    const float* x        = (const float*)d_in[1];
    const float* res_vals = (const float*)d_in[2];
    const int*   res_rows = (const int*)  d_in[3];
    const int*   res_cols = (const int*)  d_in[4];
    const float* res_bias = (const float*)d_in[5];
    const float* in_vals  = (const float*)d_in[6];
    const int*   in_rows  = (const int*)  d_in[7];
    const int*   in_cols  = (const int*)  d_in[8];
    float* out = (float*)d_out;

    int nnz_res = in_sizes[2];
    int nnz_in  = in_sizes[6];

    const int TPB = 256;

    prep_kernel<<<(N_RES * BATCH + TPB - 1) / TPB, TPB>>>(state, x, res_bias);

    int g_res = (nnz_res + 4 * TPB - 1) / (4 * TPB);
    int g_in  = (nnz_in  + 4 * TPB - 1) / (4 * TPB);
    spmm_kernel<<<g_res, TPB>>>(res_vals, res_rows, res_cols, nnz_res);
    in_spmm_kernel<<<g_in, TPB>>>(in_vals, in_rows, in_cols, nnz_in);

    finish_kernel<<<(N_RES * BATCH + TPB - 1) / TPB, TPB>>>(out);
}

// round 4
// speedup vs baseline: 2.3231x; 1.1970x over previous
#include <cuda_runtime.h>
#include <cstdint>

#define N_RES 8192
#define N_IN  256
#define BATCH 16
#define NREP  16          // accumulator replicas (power of 2)

// Scratch (device globals — runtime allocation prohibited)
__device__ __align__(256) float g_ZTR[NREP][N_RES * BATCH]; // replicated accumulators, [rep][row][b]
__device__ __align__(256) float g_ST[N_RES * BATCH];        // state^T, [col][b]
__device__ __align__(256) float g_XT[N_IN * BATCH];         // x^T, [col][b]

__device__ __forceinline__ void red_add_v4(float* addr, float a, float b, float c, float d) {
    asm volatile("red.global.add.v4.f32 [%0], {%1, %2, %3, %4};"
                 :: "l"(addr), "f"(a), "f"(b), "f"(c), "f"(d)
                 : "memory");
}

// prep: transpose state -> ST, x -> XT, zero all replicas (grid-stride)
__global__ void prep_kernel(const float* __restrict__ state,
                            const float* __restrict__ x) {
    int t = blockIdx.x * blockDim.x + threadIdx.x;
    if (t < N_RES * BATCH) {
        int b = t >> 13;
        int r = t & (N_RES - 1);
        g_ST[r * BATCH + b] = state[t];
    }
    if (t < N_IN * BATCH) {
        int b = t >> 8;
        int c = t & (N_IN - 1);
        g_XT[c * BATCH + b] = x[t];
    }
    // zero replicas: NREP * 131072 floats = 2M float4s
    float4* z = reinterpret_cast<float4*>(&g_ZTR[0][0]);
    int total4 = NREP * N_RES * BATCH / 4;
    for (int i = t; i < total4; i += gridDim.x * blockDim.x)
        z[i] = make_float4(0.f, 0.f, 0.f, 0.f);
}

// one thread per nnz; warp-selected replica spreads atomic pressure 16x
__global__ void spmm_kernel(const float* __restrict__ vals,
                            const int*   __restrict__ rows,
                            const int*   __restrict__ cols, int nnz) {
    int i = blockIdx.x * blockDim.x + threadIdx.x;
    if (i >= nnz) return;
    int rep = (i >> 5) & (NREP - 1);

    float val = vals[i];
    int   row = rows[i];
    int   col = cols[i];

    const float4* src = reinterpret_cast<const float4*>(g_ST) + col * 4;
    float4 s0 = src[0], s1 = src[1], s2 = src[2], s3 = src[3];

    float* dst = &g_ZTR[rep][row * BATCH];
    red_add_v4(dst +  0, val * s0.x, val * s0.y, val * s0.z, val * s0.w);
    red_add_v4(dst +  4, val * s1.x, val * s1.y, val * s1.z, val * s1.w);
    red_add_v4(dst +  8, val * s2.x, val * s2.y, val * s2.z, val * s2.w);
    red_add_v4(dst + 12, val * s3.x, val * s3.y, val * s3.z, val * s3.w);
}

__global__ void in_spmm_kernel(const float* __restrict__ vals,
                               const int*   __restrict__ rows,
                               const int*   __restrict__ cols, int nnz) {
    int i = blockIdx.x * blockDim.x + threadIdx.x;
    if (i >= nnz) return;
    int rep = (i >> 5) & (NREP - 1);

    float val = vals[i];
    int   row = rows[i];
    int   col = cols[i];

    const float4* src = reinterpret_cast<const float4*>(g_XT) + col * 4;
    float4 s0 = src[0], s1 = src[1], s2 = src[2], s3 = src[3];

    float* dst = &g_ZTR[rep][row * BATCH];
    red_add_v4(dst +  0, val * s0.x, val * s0.y, val * s0.z, val * s0.w);
    red_add_v4(dst +  4, val * s1.x, val * s1.y, val * s1.z, val * s1.w);
    red_add_v4(dst +  8, val * s2.x, val * s2.y, val * s2.z, val * s2.w);
    red_add_v4(dst + 12, val * s3.x, val * s3.y, val * s3.z, val * s3.w);
}

// reduce replicas + bias, apply erf, write transposed output
__global__ void finish_kernel(const float* __restrict__ bias,
                              float* __restrict__ out) {
    int t = blockIdx.x * blockDim.x + threadIdx.x;
    if (t >= N_RES * BATCH) return;
    int r = t >> 4;           // row  (consecutive t -> consecutive b: coalesced replica reads)
    int b = t & (BATCH - 1);

    float z = bias[r];
#pragma unroll
    for (int rep = 0; rep < NREP; rep++)
        z += g_ZTR[rep][t];
    out[b * N_RES + r] = erff(z);
}

extern "C" void kernel_launch(void* const* d_in, const int* in_sizes, int n_in,
                              void* d_out, int out_size) {
    const float* state    = (const float*)d_in[0];
    const float* x        = (const float*)d_in[1];
    const float* res_vals = (const float*)d_in[2];
    const int*   res_rows = (const int*)  d_in[3];
    const int*   res_cols = (const int*)  d_in[4];
    const float* res_bias = (const float*)d_in[5];
    const float* in_vals  = (const float*)d_in[6];
    const int*   in_rows  = (const int*)  d_in[7];
    const int*   in_cols  = (const int*)  d_in[8];
    float* out = (float*)d_out;

    int nnz_res = in_sizes[2];
    int nnz_in  = in_sizes[6];

    const int TPB = 256;

    prep_kernel<<<2048, TPB>>>(state, x);
    spmm_kernel<<<(nnz_res + TPB - 1) / TPB, TPB>>>(res_vals, res_rows, res_cols, nnz_res);
    in_spmm_kernel<<<(nnz_in + TPB - 1) / TPB, TPB>>>(in_vals, in_rows, in_cols, nnz_in);
    finish_kernel<<<(N_RES * BATCH + TPB - 1) / TPB, TPB>>>(res_bias, out);
}